// round 8
// baseline (speedup 1.0000x reference)
#include <cuda_runtime.h>
#include <stdint.h>

#define BB 16
#define TT 2048
#define DD 1024
#define ROWS 32                        // output rows per block
#define BLKS_PER_B (TT / ROWS)         // 64
#define BLKS (BB * BLKS_PER_B)         // 1024

// ---------------------------------------------------------------------------
// Single fused kernel, 32 rows/block to amortize the per-block scan:
//   1. mask layout detection (bool8 / int32 / int64) from first 2048 bytes
//   2. redundant per-block compaction prefix of its batch row
//      (256 threads x 8 timesteps -> bitmap -> warp+block prefix)
//   3. bit-pick the <=32 source indices in this block's output window
//   4. gather 32 rows of 4KB (8 groups of 4 float4/thread, MLP=4),
//      streaming hints (192MB stream >> 126MB L2)
// ---------------------------------------------------------------------------
__global__ void __launch_bounds__(256)
fused_kernel(const float4* __restrict__ in,
             const void* __restrict__ mask,
             float4* __restrict__ out_collected,
             float* __restrict__ out_vidx,
             float* __restrict__ out_counts) {
    const int b = blockIdx.x >> 6;               // / BLKS_PER_B
    const int j0 = (blockIdx.x & (BLKS_PER_B - 1)) * ROWS;
    const int row0 = b * TT + j0;
    const int t = threadIdx.x;
    const int warp = t >> 5;
    const int lane = t & 31;

    __shared__ int s_flags[2];
    __shared__ int s_wtot[8];
    __shared__ int s_total;
    __shared__ int s_src[ROWS];

    if (t < 2) s_flags[t] = 0;
    if (t < ROWS) s_src[t] = -1;
    __syncthreads();

    // --- 1. layout detection from first 2048 mask bytes ---
    {
        const unsigned long long det =
            ((const unsigned long long*)mask)[t];          // bytes [8t, 8t+8)
        if (det & 0xffffff00ffffff00ULL) atomicOr(&s_flags[0], 1);  // bool8
        if (det & 0x000000ff00000000ULL) atomicOr(&s_flags[1], 1);  // int32
    }
    __syncthreads();
    const int mode = s_flags[0] ? 0 : (s_flags[1] ? 1 : 2);

    // --- 2. bitmap over this thread's 8 timesteps [8t, 8t+8) of batch b ---
    unsigned bits = 0;
    if (mode == 0) {
        const unsigned long long m =
            ((const unsigned long long*)mask)[b * 256 + t];
#pragma unroll
        for (int k = 0; k < 8; k++)
            if ((m >> (8 * k)) & 0xff) bits |= 1u << k;
    } else if (mode == 1) {
        const uint4* p = (const uint4*)mask + (size_t)b * 512 + t * 2;
        const uint4 a = p[0], c = p[1];
        if (a.x) bits |= 1u;  if (a.y) bits |= 2u;
        if (a.z) bits |= 4u;  if (a.w) bits |= 8u;
        if (c.x) bits |= 16u; if (c.y) bits |= 32u;
        if (c.z) bits |= 64u; if (c.w) bits |= 128u;
    } else {
        const ulonglong2* p = (const ulonglong2*)mask + (size_t)b * 1024 + t * 4;
#pragma unroll
        for (int q = 0; q < 4; q++) {
            const ulonglong2 a = p[q];
            if (a.x) bits |= 1u << (2 * q);
            if (a.y) bits |= 1u << (2 * q + 1);
        }
    }
    const int cnt = __popc(bits);

    // --- warp + block prefix ---
    int pre = cnt;
#pragma unroll
    for (int d = 1; d < 32; d <<= 1) {
        const int n = __shfl_up_sync(0xffffffffu, pre, d);
        if (lane >= d) pre += n;
    }
    if (lane == 31) s_wtot[warp] = pre;
    __syncthreads();
    int wbase = 0;
#pragma unroll
    for (int w = 0; w < 8; w++) if (w < warp) wbase += s_wtot[w];
    const int pos0 = wbase + pre - cnt;   // exclusive prefix for this thread
    if (t == 255) s_total = wbase + pre;

    // --- 3. bit-pick sources landing in window [j0, j0+ROWS) ---
    if (pos0 < j0 + ROWS && pos0 + cnt > j0) {
        int p = pos0;
        unsigned r = bits;
        while (r) {
            const int k = __ffs(r) - 1;
            if (p >= j0) {
                if (p >= j0 + ROWS) break;
                s_src[p - j0] = t * 8 + k;
            }
            p++;
            r &= r - 1;
        }
    }
    __syncthreads();

    // --- 4. gather 32 rows, 8 groups of 4 (MLP=4) ---
    const float4* in_b = in + (size_t)(b * TT) * (DD / 4);
    float4* dst = out_collected + (size_t)row0 * (DD / 4) + t;
#pragma unroll
    for (int g = 0; g < ROWS; g += 4) {
        int src[4];
        float4 v[4];
#pragma unroll
        for (int i = 0; i < 4; i++) src[i] = s_src[g + i];
#pragma unroll
        for (int i = 0; i < 4; i++)
            v[i] = (src[i] >= 0) ? __ldcs(in_b + (size_t)src[i] * (DD / 4) + t)
                                 : make_float4(0.f, 0.f, 0.f, 0.f);
#pragma unroll
        for (int i = 0; i < 4; i++)
            __stcs(dst + (size_t)(g + i) * (DD / 4), v[i]);
    }

    if (t < ROWS) out_vidx[row0 + t] = (float)s_src[t];
    if (j0 == 0 && t == 0) out_counts[b] = (float)s_total;
}

// ---------------------------------------------------------------------------
extern "C" void kernel_launch(void* const* d_in, const int* in_sizes, int n_in,
                              void* d_out, int out_size) {
    const float* inputs = (const float*)d_in[0];   // [B, T, D] fp32
    const void* mask = d_in[1];                    // [B, T] bool

    float* out = (float*)d_out;
    float* out_collected = out;                          // B*T*D
    float* out_vidx = out + (size_t)BB * TT * DD;        // B*T
    float* out_counts = out_vidx + (size_t)BB * TT;      // B

    fused_kernel<<<BLKS, 256>>>((const float4*)inputs, mask,
                                (float4*)out_collected, out_vidx, out_counts);
}

// round 9
// speedup vs baseline: 1.1071x; 1.1071x over previous
#include <cuda_runtime.h>
#include <stdint.h>

#define BB 16
#define TT 2048
#define DD 1024
#define ROWS 8
#define BLKS ((BB * TT) / ROWS)   // 4096

// ---------------------------------------------------------------------------
// Single fused kernel (one graph node), ROWS=8 per block:
//   1. mask layout detection (bool8 / int32 / int64) by warp 0 only, each
//      block sampling a different 512B slice of the first 32KB (hotspot
//      spread across L2 slices; any aligned window classifies all layouts)
//   2. speculative mode-0 mask load issued before the detection barrier
//   3. redundant per-block compaction prefix of its batch row
//   4. bit-pick the <=8 source indices in this block's output window
//   5. gather 8 rows of 4KB (2 groups of 4 float4/thread, MLP=4),
//      streaming hints (192MB stream >> 126MB L2)
// ---------------------------------------------------------------------------
__global__ void __launch_bounds__(256)
fused_kernel(const float4* __restrict__ in,
             const void* __restrict__ mask,
             float4* __restrict__ out_collected,
             float* __restrict__ out_vidx,
             float* __restrict__ out_counts) {
    const int row0 = blockIdx.x * ROWS;
    const int b = row0 >> 11;            // ROWS divides TT; no batch crossing
    const int j0 = row0 & (TT - 1);
    const int t = threadIdx.x;
    const int warp = t >> 5;
    const int lane = t & 31;

    __shared__ int s_flags[2];
    __shared__ int s_wtot[8];
    __shared__ int s_total;
    __shared__ int s_src[ROWS];

    if (t < 2) s_flags[t] = 0;
    if (t < ROWS) s_src[t] = -1;

    // --- speculative mode-0 load (issued before any barrier) ---
    const unsigned long long m0 =
        ((const unsigned long long*)mask)[b * 256 + t];

    // --- 1. detection: warp 0, block-spread 512B slice of first 32KB ---
    if (warp == 0) {
        const size_t base = ((size_t)blockIdx.x * 512) & 32767;  // 512-aligned
        const uint4 d = ((const uint4*)((const uint8_t*)mask + base))[lane];
        // bytes at off%4!=0 nonzero => 1-byte bool
        const unsigned f123 = (d.x | d.y | d.z | d.w) & 0xffffff00u;
        // lowest byte of off%8==4 words nonzero => int32 (vs int64)
        const unsigned f4 = (d.y | d.w) & 0xffu;
        if (__ballot_sync(0xffffffffu, f123 != 0)) {
            if (lane == 0) s_flags[0] = 1;
        }
        if (__ballot_sync(0xffffffffu, f4 != 0)) {
            if (lane == 0) s_flags[1] = 1;
        }
    }
    __syncthreads();
    const int mode = s_flags[0] ? 0 : (s_flags[1] ? 1 : 2);

    // --- 2./3. bitmap over this thread's 8 timesteps [8t, 8t+8) ---
    unsigned bits = 0;
    if (mode == 0) {
#pragma unroll
        for (int k = 0; k < 8; k++)
            if ((m0 >> (8 * k)) & 0xff) bits |= 1u << k;
    } else if (mode == 1) {
        const uint4* p = (const uint4*)mask + (size_t)b * 512 + t * 2;
        const uint4 a = p[0], c = p[1];
        if (a.x) bits |= 1u;  if (a.y) bits |= 2u;
        if (a.z) bits |= 4u;  if (a.w) bits |= 8u;
        if (c.x) bits |= 16u; if (c.y) bits |= 32u;
        if (c.z) bits |= 64u; if (c.w) bits |= 128u;
    } else {
        const ulonglong2* p = (const ulonglong2*)mask + (size_t)b * 1024 + t * 4;
#pragma unroll
        for (int q = 0; q < 4; q++) {
            const ulonglong2 a = p[q];
            if (a.x) bits |= 1u << (2 * q);
            if (a.y) bits |= 1u << (2 * q + 1);
        }
    }
    const int cnt = __popc(bits);

    // --- warp + block prefix ---
    int pre = cnt;
#pragma unroll
    for (int d = 1; d < 32; d <<= 1) {
        const int n = __shfl_up_sync(0xffffffffu, pre, d);
        if (lane >= d) pre += n;
    }
    if (lane == 31) s_wtot[warp] = pre;
    __syncthreads();
    int wbase = 0;
#pragma unroll
    for (int w = 0; w < 8; w++) if (w < warp) wbase += s_wtot[w];
    const int pos0 = wbase + pre - cnt;   // exclusive prefix for this thread
    if (t == 255) s_total = wbase + pre;

    // --- 4. bit-pick sources landing in window [j0, j0+ROWS) ---
    if (pos0 < j0 + ROWS && pos0 + cnt > j0) {
        int p = pos0;
        unsigned r = bits;
        while (r) {
            const int k = __ffs(r) - 1;
            if (p >= j0) {
                if (p >= j0 + ROWS) break;
                s_src[p - j0] = t * 8 + k;
            }
            p++;
            r &= r - 1;
        }
    }
    __syncthreads();

    // --- 5. gather 8 rows, 2 groups of 4 (MLP=4) ---
    const float4* in_b = in + (size_t)(b * TT) * (DD / 4);
    float4* dst = out_collected + (size_t)row0 * (DD / 4) + t;
#pragma unroll
    for (int half = 0; half < 2; half++) {
        int src[4];
        float4 v[4];
#pragma unroll
        for (int i = 0; i < 4; i++) src[i] = s_src[half * 4 + i];
#pragma unroll
        for (int i = 0; i < 4; i++)
            v[i] = (src[i] >= 0) ? __ldcs(in_b + (size_t)src[i] * (DD / 4) + t)
                                 : make_float4(0.f, 0.f, 0.f, 0.f);
#pragma unroll
        for (int i = 0; i < 4; i++)
            __stcs(dst + (size_t)(half * 4 + i) * (DD / 4), v[i]);
    }

    if (t < ROWS) out_vidx[row0 + t] = (float)s_src[t];
    if (j0 == 0 && t == 0) out_counts[b] = (float)s_total;
}

// ---------------------------------------------------------------------------
extern "C" void kernel_launch(void* const* d_in, const int* in_sizes, int n_in,
                              void* d_out, int out_size) {
    const float* inputs = (const float*)d_in[0];   // [B, T, D] fp32
    const void* mask = d_in[1];                    // [B, T] bool

    float* out = (float*)d_out;
    float* out_collected = out;                          // B*T*D
    float* out_vidx = out + (size_t)BB * TT * DD;        // B*T
    float* out_counts = out_vidx + (size_t)BB * TT;      // B

    fused_kernel<<<BLKS, 256>>>((const float4*)inputs, mask,
                                (float4*)out_collected, out_vidx, out_counts);
}